// round 3
// baseline (speedup 1.0000x reference)
#include <cuda_runtime.h>
#include <cuda_bf16.h>
#include <math.h>

#define BB 4
#define CC 64
#define OO 64
#define HH 128
#define WW 128
#define CHS (HH * WW)

#define WPAD 68                 // main weight row floats
#define OPAD 28                 // offset weight row floats
#define WROWB (WPAD * 4)        // 272 bytes
#define OROWB (OPAD * 4)        // 112 bytes

// -------- packed f32x2 helpers --------
__device__ __forceinline__ unsigned long long pack2(float lo, float hi) {
    unsigned long long r;
    asm("mov.b64 %0, {%1, %2};" : "=l"(r) : "f"(lo), "f"(hi));
    return r;
}
__device__ __forceinline__ void unpack2(unsigned long long v, float& lo, float& hi) {
    asm("mov.b64 {%0, %1}, %2;" : "=f"(lo), "=f"(hi) : "l"(v));
}
__device__ __forceinline__ unsigned long long ffma2(unsigned long long a,
                                                    unsigned long long b,
                                                    unsigned long long c) {
    unsigned long long d;
    asm("fma.rn.f32x2 %0, %1, %2, %3;" : "=l"(d) : "l"(a), "l"(b), "l"(c));
    return d;
}

// ---------------------------------------------------------------------------
// Fused DCNv2+BN+ReLU. Block = 512 threads = 2 rows; a pixel is owned by a
// lane PAIR (lane, lane^16): gathers split by tap and exchanged via shuffles,
// outputs split 32/32. Weight LDS reads are bank-disjoint across the halves
// via a per-half tap-order rotation, so paired reads cost 1 wavefront.
// ---------------------------------------------------------------------------
__global__ void __launch_bounds__(512, 1) dcn_fused2_kernel(
    const float* __restrict__ x,
    const float* __restrict__ w_off,
    const float* __restrict__ b_off,
    const float* __restrict__ weight,
    const float* __restrict__ bias,
    const float* __restrict__ gamma,
    const float* __restrict__ beta,
    const float* __restrict__ rmean,
    const float* __restrict__ rvar,
    float* __restrict__ out)
{
    extern __shared__ float sm[];
    float* wsh    = sm;                          // [576][WPAD]
    float* wosh   = sm + 576 * WPAD;             // [576][OPAD]
    float* bscale = wosh + 576 * OPAD;           // [64]
    float* bshift = bscale + 64;                 // [64]

    const int tid  = threadIdx.x;
    const int lane = tid & 31;
    const int warp = tid >> 5;
    const int half = lane >> 4;                  // 0/1: output half + tap group
    const int p    = warp * 16 + (lane & 15);    // pixel in CTA [0,256)
    const int gr   = blockIdx.x * 2 + (p >> 7);  // global row [0,512)
    const int b    = gr >> 7;
    const int h    = gr & 127;
    const int w    = p & 127;

    // ---- stage weights ----
    for (int i = tid; i < OO * 576; i += 512) {
        int o = i / 576, ck = i % 576;
        wsh[ck * WPAD + o] = weight[i];
    }
    for (int i = tid; i < 27 * 576; i += 512) {
        int oc = i / 576, ck = i % 576;
        wosh[ck * OPAD + oc] = w_off[i];
    }
    for (int i = tid; i < 576; i += 512) wosh[i * OPAD + 27] = 0.0f;
    if (tid < 64) {
        int o = tid;
        float sc = gamma[o] * rsqrtf(rvar[o] + 1e-5f);
        bscale[o] = sc;
        bshift[o] = (bias[o] - rmean[o]) * sc + beta[o];
    }
    __syncthreads();

    const float* xb = x + (size_t)b * CC * CHS;

    // per-lane tap-order row offsets (bytes) for the weight FMA loops
    const int perm2[9] = {5, 6, 7, 8, 4, 0, 1, 2, 3};
    int kofs1[9], kofs2[9];
#pragma unroll
    for (int i = 0; i < 9; i++) {
        kofs1[i] = (half ? (4 + i) % 9 : i) * OROWB;
        kofs2[i] = (half ? perm2[i] : i) * WROWB;
    }

    // =======================================================================
    // Phase 1: offset conv. half0 gathers taps 0..4, half1 taps 4..8;
    // each half accumulates offset channels [14*half, 14*half+14).
    // =======================================================================
    int p1o[5]; bool p1v[5];
    {
        const int ty0[5] = {-1, -1, -1, 0, 0}, tx0[5] = {-1, 0, 1, -1, 0};
        const int ty1[5] = {0, 0, 1, 1, 1},    tx1[5] = {0, 1, -1, 0, 1};
#pragma unroll
        for (int j = 0; j < 5; j++) {
            int ty = half ? ty1[j] : ty0[j];
            int tx = half ? tx1[j] : tx0[j];
            int y = h + ty, xx = w + tx;
            p1v[j] = (y >= 0) & (y < HH) & (xx >= 0) & (xx < WW);
            p1o[j] = y * WW + xx;
        }
    }

    unsigned long long offa[7];
    {
        int ocb = half * 14;
#pragma unroll
        for (int j = 0; j < 7; j++) {
            int i1 = ocb + 2 * j + 1;
            float lo = b_off[ocb + 2 * j];
            float hi = (i1 < 27) ? b_off[i1] : 0.0f;
            offa[j] = pack2(lo, hi);
        }
    }

    {
        const char* wo_base = (const char*)wosh + half * 56;
        for (int c = 0; c < CC; c++) {
            const float* xc = xb + c * CHS;
            float xq[5];
#pragma unroll
            for (int j = 0; j < 5; j++)
                xq[j] = p1v[j] ? __ldg(xc + p1o[j]) : 0.0f;
            // exchange: half0 sends taps0..3, half1 sends taps5..8
            float r0 = __shfl_xor_sync(0xffffffffu, half ? xq[1] : xq[0], 16);
            float r1 = __shfl_xor_sync(0xffffffffu, half ? xq[2] : xq[1], 16);
            float r2 = __shfl_xor_sync(0xffffffffu, half ? xq[3] : xq[2], 16);
            float r3 = __shfl_xor_sync(0xffffffffu, half ? xq[4] : xq[3], 16);
            unsigned long long X[9];
            X[0] = pack2(xq[0], xq[0]); X[1] = pack2(xq[1], xq[1]);
            X[2] = pack2(xq[2], xq[2]); X[3] = pack2(xq[3], xq[3]);
            X[4] = pack2(xq[4], xq[4]);
            X[5] = pack2(r0, r0); X[6] = pack2(r1, r1);
            X[7] = pack2(r2, r2); X[8] = pack2(r3, r3);
            const char* rowc = wo_base + c * (9 * OROWB);
#pragma unroll
            for (int i = 0; i < 9; i++) {
                const unsigned long long* wp =
                    (const unsigned long long*)(rowc + kofs1[i]);
#pragma unroll
                for (int j2 = 0; j2 < 7; j2++)
                    offa[j2] = ffma2(wp[j2], X[i], offa[j2]);
            }
        }
    }

    // =======================================================================
    // Geometry. Exchange the cross-half offset/mask values (6 shuffles), then
    // build cf/ofs for this lane's taps: half0 -> taps 0..3 (+tap4 top row),
    // half1 -> taps 5..8 (+tap4 bottom row).
    // =======================================================================
    float l[14];
#pragma unroll
    for (int j = 0; j < 7; j++) unpack2(offa[j], l[2 * j], l[2 * j + 1]);
    float g[6];
#pragma unroll
    for (int i = 0; i < 6; i++)
        g[i] = __shfl_xor_sync(0xffffffffu, half ? l[4 + i] : l[8 + i], 16);

    float oyv[4], oxv[4], mrv[4];
    oyv[0] = half ? g[2] : l[0];  oxv[0] = half ? g[3] : l[1];  mrv[0] = half ? l[9]  : g[0];
    oyv[1] = half ? g[4] : l[2];  oxv[1] = half ? g[5] : l[3];  mrv[1] = half ? l[10] : g[1];
    oyv[2] = half ? l[0] : l[4];  oxv[2] = half ? l[1] : l[5];  mrv[2] = half ? l[11] : g[2];
    oyv[3] = half ? l[2] : l[6];  oxv[3] = half ? l[3] : l[7];  mrv[3] = half ? l[12] : g[3];
    float oy4 = half ? g[0] : l[8];
    float ox4 = half ? g[1] : l[9];
    float mr4 = half ? l[8] : g[4];

    float cf[4][4]; int ofs[4][4];
    {
        const int mty0[4] = {-1, -1, -1, 0}, mtx0[4] = {-1, 0, 1, -1};
        const int mty1[4] = {0, 1, 1, 1},    mtx1[4] = {1, -1, 0, 1};
#pragma unroll
        for (int j = 0; j < 4; j++) {
            int ty = half ? mty1[j] : mty0[j];
            int tx = half ? mtx1[j] : mtx0[j];
            float m = 1.0f / (1.0f + __expf(-mrv[j]));
            float py = (float)(h + ty) + oyv[j];
            float px = (float)(w + tx) + oxv[j];
            float y0f = floorf(py), x0f = floorf(px);
            float dy = py - y0f, dx = px - x0f;
            int y0 = (int)y0f, x0 = (int)x0f;
            int y1 = y0 + 1,   x1 = x0 + 1;
            bool vy0 = (y0 >= 0) & (y0 < HH), vy1 = (y1 >= 0) & (y1 < HH);
            bool vx0 = (x0 >= 0) & (x0 < WW), vx1 = (x1 >= 0) & (x1 < WW);
            int cy0 = min(max(y0, 0), HH - 1), cy1 = min(max(y1, 0), HH - 1);
            int cx0 = min(max(x0, 0), WW - 1), cx1 = min(max(x1, 0), WW - 1);
            ofs[j][0] = cy0 * WW + cx0;  cf[j][0] = (vy0 && vx0) ? (1.0f - dy) * (1.0f - dx) * m : 0.0f;
            ofs[j][1] = cy0 * WW + cx1;  cf[j][1] = (vy0 && vx1) ? (1.0f - dy) * dx * m          : 0.0f;
            ofs[j][2] = cy1 * WW + cx0;  cf[j][2] = (vy1 && vx0) ? dy * (1.0f - dx) * m          : 0.0f;
            ofs[j][3] = cy1 * WW + cx1;  cf[j][3] = (vy1 && vx1) ? dy * dx * m                   : 0.0f;
        }
    }
    float cf4[2]; int ofs4[2];
    {
        float m = 1.0f / (1.0f + __expf(-mr4));
        float py = (float)h + oy4;
        float px = (float)w + ox4;
        float y0f = floorf(py), x0f = floorf(px);
        float dy = py - y0f, dx = px - x0f;
        int y0 = (int)y0f, x0 = (int)x0f;
        int y1 = y0 + 1,   x1 = x0 + 1;
        bool vy0 = (y0 >= 0) & (y0 < HH), vy1 = (y1 >= 0) & (y1 < HH);
        bool vx0 = (x0 >= 0) & (x0 < WW), vx1 = (x1 >= 0) & (x1 < WW);
        int cy0 = min(max(y0, 0), HH - 1), cy1 = min(max(y1, 0), HH - 1);
        int cx0 = min(max(x0, 0), WW - 1), cx1 = min(max(x1, 0), WW - 1);
        bool rowv = half ? vy1 : vy0;
        int  crow = half ? cy1 : cy0;
        float ca  = half ? dy : (1.0f - dy);
        cf4[0] = (rowv && vx0) ? ca * (1.0f - dx) * m : 0.0f;
        cf4[1] = (rowv && vx1) ? ca * dx * m          : 0.0f;
        ofs4[0] = crow * WW + cx0;
        ofs4[1] = crow * WW + cx1;
    }

    // =======================================================================
    // Phase 2: deformable conv. Each lane gathers its taps, exchanges vals
    // with its partner (5 shuffles), accumulates its 32-output half.
    // =======================================================================
    unsigned long long acc[16];
#pragma unroll
    for (int j = 0; j < 16; j++) acc[j] = 0ULL;

    const char* w2base = (const char*)wsh + half * 128;

    for (int c = 0; c < CC; c++) {
        const float* xc = xb + c * CHS;
        float v[5];
#pragma unroll
        for (int j = 0; j < 4; j++) {
            v[j] = cf[j][0] * __ldg(xc + ofs[j][0])
                 + cf[j][1] * __ldg(xc + ofs[j][1])
                 + cf[j][2] * __ldg(xc + ofs[j][2])
                 + cf[j][3] * __ldg(xc + ofs[j][3]);
        }
        v[4] = cf4[0] * __ldg(xc + ofs4[0]) + cf4[1] * __ldg(xc + ofs4[1]);

        float q0 = __shfl_xor_sync(0xffffffffu, v[0], 16);
        float q1 = __shfl_xor_sync(0xffffffffu, v[1], 16);
        float q2 = __shfl_xor_sync(0xffffffffu, v[2], 16);
        float q3 = __shfl_xor_sync(0xffffffffu, v[3], 16);
        v[4] += __shfl_xor_sync(0xffffffffu, v[4], 16);

        unsigned long long V[9];
        V[0] = pack2(v[0], v[0]); V[1] = pack2(v[1], v[1]);
        V[2] = pack2(v[2], v[2]); V[3] = pack2(v[3], v[3]);
        V[4] = pack2(v[4], v[4]);
        V[5] = pack2(q0, q0); V[6] = pack2(q1, q1);
        V[7] = pack2(q2, q2); V[8] = pack2(q3, q3);

        const char* rowc = w2base + c * (9 * WROWB);
#pragma unroll
        for (int i = 0; i < 9; i++) {
            const ulonglong2* wp = (const ulonglong2*)(rowc + kofs2[i]);
#pragma unroll
            for (int q = 0; q < 8; q++) {
                ulonglong2 ww = wp[q];
                acc[2 * q]     = ffma2(ww.x, V[i], acc[2 * q]);
                acc[2 * q + 1] = ffma2(ww.y, V[i], acc[2 * q + 1]);
            }
        }
    }

    // =======================================================================
    // BN + ReLU + store (NCHW): this lane's 32 outputs
    // =======================================================================
    float* op = out + ((size_t)b * OO + half * 32) * CHS + h * WW + w;
#pragma unroll
    for (int j = 0; j < 16; j++) {
        float lo, hi;
        unpack2(acc[j], lo, hi);
        int o = half * 32 + 2 * j;
        op[(size_t)(2 * j) * CHS]     = fmaxf(lo * bscale[o]     + bshift[o],     0.0f);
        op[(size_t)(2 * j + 1) * CHS] = fmaxf(hi * bscale[o + 1] + bshift[o + 1], 0.0f);
    }
}

// ---------------------------------------------------------------------------

extern "C" void kernel_launch(void* const* d_in, const int* in_sizes, int n_in,
                              void* d_out, int out_size)
{
    const float* x      = (const float*)d_in[0];
    const float* w_off  = (const float*)d_in[1];
    const float* b_off  = (const float*)d_in[2];
    const float* weight = (const float*)d_in[3];
    const float* bias   = (const float*)d_in[4];
    const float* gamma  = (const float*)d_in[5];
    const float* beta   = (const float*)d_in[6];
    const float* rmean  = (const float*)d_in[7];
    const float* rvar   = (const float*)d_in[8];
    float* out = (float*)d_out;

    const int smem = (576 * WPAD + 576 * OPAD + 128) * sizeof(float); // ~216.5 KB

    cudaFuncSetAttribute(dcn_fused2_kernel,
                         cudaFuncAttributeMaxDynamicSharedMemorySize, smem);

    dcn_fused2_kernel<<<BB * HH / 2, 512, smem>>>(
        x, w_off, b_off, weight, bias, gamma, beta, rmean, rvar, out);
}

// round 4
// speedup vs baseline: 1.0997x; 1.0997x over previous
#include <cuda_runtime.h>
#include <cuda_bf16.h>
#include <math.h>

#define BB 4
#define CC 64
#define OO 64
#define HH 128
#define WW 128
#define CHS (HH * WW)

#define WPAD 68                     // main weight row floats (272B, 16B-aligned)
// SMEM float offsets
#define WSH_F   0
#define UNI_F   (576 * WPAD)        // 39168
#define EXSH_F  UNI_F               // 28 x 260 = 7280 floats (after phase 1)
#define VSH_F   (UNI_F + 7296)      // 2 x 10 x 256 = 5120 floats
#define BN_F    (UNI_F + 576 * 32)  // 57600
#define SMEM_FLOATS (BN_F + 128)    // 57728 -> 230912 bytes

typedef unsigned long long ull;

__device__ __forceinline__ ull pack2(float lo, float hi) {
    ull r; asm("mov.b64 %0, {%1, %2};" : "=l"(r) : "f"(lo), "f"(hi)); return r;
}
__device__ __forceinline__ void unpack2(ull v, float& lo, float& hi) {
    asm("mov.b64 {%0, %1}, %2;" : "=f"(lo), "=f"(hi) : "l"(v));
}
__device__ __forceinline__ ull ffma2(ull a, ull b, ull c) {
    ull d; asm("fma.rn.f32x2 %0, %1, %2, %3;" : "=l"(d) : "l"(a), "l"(b), "l"(c)); return d;
}
__device__ __forceinline__ ull addf2(ull a, ull b) {
    ull d; asm("add.rn.f32x2 %0, %1, %2;" : "=l"(d) : "l"(a), "l"(b)); return d;
}

// ---------------------------------------------------------------------------
// Fused DCNv2 + BN + ReLU, one CTA = 2 image rows (256 px), 512 threads.
// Per channel: sampler step stages bilinear tap values into SMEM (vsh),
// then a register-tiled (4 outputs x 8 px) FMA pass consumes them.
// ---------------------------------------------------------------------------
__global__ void __launch_bounds__(512, 1) dcn_fused3_kernel(
    const float* __restrict__ x,
    const float* __restrict__ w_off,
    const float* __restrict__ b_off,
    const float* __restrict__ weight,
    const float* __restrict__ bias,
    const float* __restrict__ gamma,
    const float* __restrict__ beta,
    const float* __restrict__ rmean,
    const float* __restrict__ rvar,
    float* __restrict__ out)
{
    extern __shared__ float sm[];
    float* wsh    = sm + WSH_F;      // [576][WPAD]
    float* wosh   = sm + UNI_F;      // [576][32] (phase 1 only)
    float* exsh   = sm + EXSH_F;     // [28][260] (after phase 1)
    float* vsh    = sm + VSH_F;      // [2][10][256]
    float* bscale = sm + BN_F;
    float* bshift = bscale + 64;

    const int tid  = threadIdx.x;
    const int lane = tid & 31;
    const int w2   = tid >> 5;

    // ---------------- staging ----------------
    for (int i = tid; i < OO * 576; i += 512) {
        int o = i / 576, ck = i % 576;
        wsh[ck * WPAD + o] = weight[i];
    }
    for (int i = tid; i < 576 * 32; i += 512) wosh[i] = 0.0f;
    if (tid < 64) {
        int o = tid;
        float sc = gamma[o] * rsqrtf(rvar[o] + 1e-5f);
        bscale[o] = sc;
        bshift[o] = (bias[o] - rmean[o]) * sc + beta[o];
    }
    __syncthreads();
    for (int i = tid; i < 27 * 576; i += 512) {
        int oc = i / 576, ck = i % 576;
        int hf = (oc >= 14), j = oc - 14 * hf;
        wosh[ck * 32 + hf * 16 + j] = w_off[i];
    }
    __syncthreads();

    // CTA-uniform batch
    const int gr0 = blockIdx.x * 2;
    const int b   = gr0 >> 7;
    const float* xb = x + (size_t)b * CC * CHS;

    // =======================================================================
    // Phase 1: offset conv. Pairing (lane, lane^16) within a warp; each half
    // gathers 5 taps, exchanges 4 via shuffle, accumulates 14 offset chans.
    // =======================================================================
    {
        const int p     = w2 * 16 + (lane & 15);   // pixel 0..255
        const int halfp = lane >> 4;
        const int hp    = (gr0 + (p >> 7)) & 127;
        const int wp_   = p & 127;

        const int ty0[5] = {-1, -1, -1, 0, 0}, tx0[5] = {-1, 0, 1, -1, 0};
        const int ty1[5] = {0, 0, 1, 1, 1},    tx1[5] = {0, 1, -1, 0, 1};
        int p1o[5]; bool p1v[5];
#pragma unroll
        for (int j = 0; j < 5; j++) {
            int ty = halfp ? ty1[j] : ty0[j];
            int tx = halfp ? tx1[j] : tx0[j];
            int y = hp + ty, xx = wp_ + tx;
            p1v[j] = (y >= 0) & (y < HH) & (xx >= 0) & (xx < WW);
            p1o[j] = y * WW + xx;
        }
        int kord[9];
#pragma unroll
        for (int i = 0; i < 9; i++) kord[i] = halfp ? (4 + i) % 9 : i;

        ull offa[7];
        {
            int chb = halfp * 14;
#pragma unroll
            for (int j = 0; j < 7; j++) {
                int i1 = chb + 2 * j + 1;
                float lo = b_off[chb + 2 * j];
                float hi = (i1 < 27) ? b_off[i1] : 0.0f;
                offa[j] = pack2(lo, hi);
            }
        }

        const float* wbase = wosh + halfp * 16;
        for (int c = 0; c < CC; c++) {
            const float* xc = xb + c * CHS;
            float xq[5];
#pragma unroll
            for (int j = 0; j < 5; j++)
                xq[j] = p1v[j] ? __ldg(xc + p1o[j]) : 0.0f;
            float r0 = __shfl_xor_sync(0xffffffffu, halfp ? xq[1] : xq[0], 16);
            float r1 = __shfl_xor_sync(0xffffffffu, halfp ? xq[2] : xq[1], 16);
            float r2 = __shfl_xor_sync(0xffffffffu, halfp ? xq[3] : xq[2], 16);
            float r3 = __shfl_xor_sync(0xffffffffu, halfp ? xq[4] : xq[3], 16);
            ull X[9];
            X[0] = pack2(xq[0], xq[0]); X[1] = pack2(xq[1], xq[1]);
            X[2] = pack2(xq[2], xq[2]); X[3] = pack2(xq[3], xq[3]);
            X[4] = pack2(xq[4], xq[4]);
            X[5] = pack2(r0, r0); X[6] = pack2(r1, r1);
            X[7] = pack2(r2, r2); X[8] = pack2(r3, r3);

            const float* crow = wbase + c * 288;
#pragma unroll
            for (int i = 0; i < 9; i++) {
                const float* wp2 = crow + kord[i] * 32;
                ulonglong2 q0 = ((const ulonglong2*)wp2)[0];
                ulonglong2 q1 = ((const ulonglong2*)wp2)[1];
                ulonglong2 q2 = ((const ulonglong2*)wp2)[2];
                ull        q6 = ((const ull*)wp2)[6];
                offa[0] = ffma2(q0.x, X[i], offa[0]);
                offa[1] = ffma2(q0.y, X[i], offa[1]);
                offa[2] = ffma2(q1.x, X[i], offa[2]);
                offa[3] = ffma2(q1.y, X[i], offa[3]);
                offa[4] = ffma2(q2.x, X[i], offa[4]);
                offa[5] = ffma2(q2.y, X[i], offa[5]);
                offa[6] = ffma2(q6,   X[i], offa[6]);
            }
        }

        __syncthreads();   // all wosh reads done; exsh may overwrite
        {
            float l[14];
#pragma unroll
            for (int j = 0; j < 7; j++) unpack2(offa[j], l[2 * j], l[2 * j + 1]);
            int chb = halfp * 14;
#pragma unroll
            for (int j = 0; j < 14; j++)
                exsh[(chb + j) * 260 + p] = l[j];
        }
        __syncthreads();
    }

    // =======================================================================
    // Geometry (sampler identity): spx = pixel, sh = tap-half.
    // sh0 -> taps {0,1,2,3} + tap4 top row; sh1 -> taps {5,6,7,8} + bottom.
    // =======================================================================
    const int spx = ((w2 & 7) << 5) | lane;
    const int sh  = w2 >> 3;
    const int shh = (gr0 + (spx >> 7)) & 127;
    const int sww = spx & 127;

    float cf[4][4]; int ofs[4][4];
    float cf4[2];   int ofs4[2];
#pragma unroll
    for (int j = 0; j < 4; j++) {
        int k = sh ? 5 + j : j;
        float oy = exsh[(2 * k) * 260 + spx];
        float ox = exsh[(2 * k + 1) * 260 + spx];
        float m  = 1.0f / (1.0f + __expf(-exsh[(18 + k) * 260 + spx]));
        float py = (float)(shh + k / 3 - 1) + oy;
        float px = (float)(sww + k % 3 - 1) + ox;
        float y0f = floorf(py), x0f = floorf(px);
        float dy = py - y0f, dx = px - x0f;
        int y0 = (int)y0f, x0 = (int)x0f;
        int y1 = y0 + 1,   x1 = x0 + 1;
        bool vy0 = (y0 >= 0) & (y0 < HH), vy1 = (y1 >= 0) & (y1 < HH);
        bool vx0 = (x0 >= 0) & (x0 < WW), vx1 = (x1 >= 0) & (x1 < WW);
        int cy0 = min(max(y0, 0), HH - 1), cy1 = min(max(y1, 0), HH - 1);
        int cx0 = min(max(x0, 0), WW - 1), cx1 = min(max(x1, 0), WW - 1);
        ofs[j][0] = cy0 * WW + cx0;  cf[j][0] = (vy0 && vx0) ? (1.0f - dy) * (1.0f - dx) * m : 0.0f;
        ofs[j][1] = cy0 * WW + cx1;  cf[j][1] = (vy0 && vx1) ? (1.0f - dy) * dx * m          : 0.0f;
        ofs[j][2] = cy1 * WW + cx0;  cf[j][2] = (vy1 && vx0) ? dy * (1.0f - dx) * m          : 0.0f;
        ofs[j][3] = cy1 * WW + cx1;  cf[j][3] = (vy1 && vx1) ? dy * dx * m                   : 0.0f;
    }
    {
        float oy = exsh[8 * 260 + spx];
        float ox = exsh[9 * 260 + spx];
        float m  = 1.0f / (1.0f + __expf(-exsh[22 * 260 + spx]));
        float py = (float)shh + oy;
        float px = (float)sww + ox;
        float y0f = floorf(py), x0f = floorf(px);
        float dy = py - y0f, dx = px - x0f;
        int y0 = (int)y0f, x0 = (int)x0f;
        int y1 = y0 + 1,   x1 = x0 + 1;
        bool vy0 = (y0 >= 0) & (y0 < HH), vy1 = (y1 >= 0) & (y1 < HH);
        bool vx0 = (x0 >= 0) & (x0 < WW), vx1 = (x1 >= 0) & (x1 < WW);
        int cy0 = min(max(y0, 0), HH - 1), cy1 = min(max(y1, 0), HH - 1);
        int cx0 = min(max(x0, 0), WW - 1), cx1 = min(max(x1, 0), WW - 1);
        bool rowv = sh ? vy1 : vy0;
        int  crow = sh ? cy1 : cy0;
        float ca  = sh ? dy : (1.0f - dy);
        cf4[0] = (rowv && vx0) ? ca * (1.0f - dx) * m : 0.0f;
        cf4[1] = (rowv && vx1) ? ca * dx * m          : 0.0f;
        ofs4[0] = crow * WW + cx0;
        ofs4[1] = crow * WW + cx1;
    }
    const int vrow0 = sh ? 6 : 0;     // base row for the 4 full taps
    const int vrowp = 4 + sh;         // partial (tap4) row

    // producer: stage this channel's tap values into vsh[buf]
    auto produce = [&](int c, int buf) {
        const float* xc = xb + c * CHS;
        float v0 = cf[0][0] * __ldg(xc + ofs[0][0]) + cf[0][1] * __ldg(xc + ofs[0][1])
                 + cf[0][2] * __ldg(xc + ofs[0][2]) + cf[0][3] * __ldg(xc + ofs[0][3]);
        float v1 = cf[1][0] * __ldg(xc + ofs[1][0]) + cf[1][1] * __ldg(xc + ofs[1][1])
                 + cf[1][2] * __ldg(xc + ofs[1][2]) + cf[1][3] * __ldg(xc + ofs[1][3]);
        float v2 = cf[2][0] * __ldg(xc + ofs[2][0]) + cf[2][1] * __ldg(xc + ofs[2][1])
                 + cf[2][2] * __ldg(xc + ofs[2][2]) + cf[2][3] * __ldg(xc + ofs[2][3]);
        float v3 = cf[3][0] * __ldg(xc + ofs[3][0]) + cf[3][1] * __ldg(xc + ofs[3][1])
                 + cf[3][2] * __ldg(xc + ofs[3][2]) + cf[3][3] * __ldg(xc + ofs[3][3]);
        float vp = cf4[0] * __ldg(xc + ofs4[0]) + cf4[1] * __ldg(xc + ofs4[1]);
        float* vo = vsh + buf * 2560 + spx;
        vo[(vrow0 + 0) * 256] = v0;
        vo[(vrow0 + 1) * 256] = v1;
        vo[(vrow0 + 2) * 256] = v2;
        vo[(vrow0 + 3) * 256] = v3;
        vo[vrowp * 256]       = vp;
    };

    // =======================================================================
    // Main loop: register-tiled FMA pass (4 outputs x 8 px per thread)
    // =======================================================================
    const int og  = (lane & 7) | ((w2 & 1) << 3);      // 0..15 (4 outputs each)
    const int pxg = (lane >> 3) | ((w2 >> 1) << 2);    // 0..31 (8 px each)

    ull acc[16];
#pragma unroll
    for (int j = 0; j < 16; j++) acc[j] = 0ULL;

    produce(0, 0);

    for (int c = 0; c < CC; c++) {
        __syncthreads();
        if (c < CC - 1) produce(c + 1, (c + 1) & 1);

        const float* wr = wsh + c * (9 * WPAD) + og * 4;
        const float* vb = vsh + (c & 1) * 2560 + pxg * 8;
#pragma unroll
        for (int k = 0; k < 9; k++) {
            float4 wv = *(const float4*)(wr + k * WPAD);
            ull w0 = pack2(wv.x, wv.x);
            ull w1 = pack2(wv.y, wv.y);
            ull wq = pack2(wv.z, wv.z);
            ull w3 = pack2(wv.w, wv.w);

            ulonglong2 va, vb2;
            if (k == 4) {
                ulonglong2 a0 = ((const ulonglong2*)(vb + 4 * 256))[0];
                ulonglong2 a1 = ((const ulonglong2*)(vb + 4 * 256))[1];
                ulonglong2 b0 = ((const ulonglong2*)(vb + 5 * 256))[0];
                ulonglong2 b1 = ((const ulonglong2*)(vb + 5 * 256))[1];
                va.x  = addf2(a0.x, b0.x);  va.y  = addf2(a0.y, b0.y);
                vb2.x = addf2(a1.x, b1.x);  vb2.y = addf2(a1.y, b1.y);
            } else {
                int vr = (k < 4) ? k : k + 1;
                va  = ((const ulonglong2*)(vb + vr * 256))[0];
                vb2 = ((const ulonglong2*)(vb + vr * 256))[1];
            }
            acc[0]  = ffma2(w0, va.x,  acc[0]);
            acc[1]  = ffma2(w0, va.y,  acc[1]);
            acc[2]  = ffma2(w0, vb2.x, acc[2]);
            acc[3]  = ffma2(w0, vb2.y, acc[3]);
            acc[4]  = ffma2(w1, va.x,  acc[4]);
            acc[5]  = ffma2(w1, va.y,  acc[5]);
            acc[6]  = ffma2(w1, vb2.x, acc[6]);
            acc[7]  = ffma2(w1, vb2.y, acc[7]);
            acc[8]  = ffma2(wq, va.x,  acc[8]);
            acc[9]  = ffma2(wq, va.y,  acc[9]);
            acc[10] = ffma2(wq, vb2.x, acc[10]);
            acc[11] = ffma2(wq, vb2.y, acc[11]);
            acc[12] = ffma2(w3, va.x,  acc[12]);
            acc[13] = ffma2(w3, va.y,  acc[13]);
            acc[14] = ffma2(w3, vb2.x, acc[14]);
            acc[15] = ffma2(w3, vb2.y, acc[15]);
        }
    }

    // =======================================================================
    // BN + ReLU + store. Thread owns outputs og*4..+3, pixels pxg*8..+7.
    // =======================================================================
    const int cgr = gr0 + (pxg >> 4);
    const int chh = cgr & 127;
    const int cww = (pxg & 15) * 8;
    float* op = out + ((size_t)(b * OO + og * 4)) * CHS + chh * WW + cww;

#pragma unroll
    for (int oi = 0; oi < 4; oi++) {
        float sc = bscale[og * 4 + oi];
        float sf = bshift[og * 4 + oi];
        float a0, a1, a2, a3, a4, a5, a6, a7;
        unpack2(acc[oi * 4 + 0], a0, a1);
        unpack2(acc[oi * 4 + 1], a2, a3);
        unpack2(acc[oi * 4 + 2], a4, a5);
        unpack2(acc[oi * 4 + 3], a6, a7);
        float4 f0 = { fmaxf(a0 * sc + sf, 0.0f), fmaxf(a1 * sc + sf, 0.0f),
                      fmaxf(a2 * sc + sf, 0.0f), fmaxf(a3 * sc + sf, 0.0f) };
        float4 f1 = { fmaxf(a4 * sc + sf, 0.0f), fmaxf(a5 * sc + sf, 0.0f),
                      fmaxf(a6 * sc + sf, 0.0f), fmaxf(a7 * sc + sf, 0.0f) };
        *(float4*)(op + (size_t)oi * CHS)     = f0;
        *(float4*)(op + (size_t)oi * CHS + 4) = f1;
    }
}

// ---------------------------------------------------------------------------

extern "C" void kernel_launch(void* const* d_in, const int* in_sizes, int n_in,
                              void* d_out, int out_size)
{
    const float* x      = (const float*)d_in[0];
    const float* w_off  = (const float*)d_in[1];
    const float* b_off  = (const float*)d_in[2];
    const float* weight = (const float*)d_in[3];
    const float* bias   = (const float*)d_in[4];
    const float* gamma  = (const float*)d_in[5];
    const float* beta   = (const float*)d_in[6];
    const float* rmean  = (const float*)d_in[7];
    const float* rvar   = (const float*)d_in[8];
    float* out = (float*)d_out;

    const int smem = SMEM_FLOATS * sizeof(float);   // 230,912 B

    cudaFuncSetAttribute(dcn_fused3_kernel,
                         cudaFuncAttributeMaxDynamicSharedMemorySize, smem);

    dcn_fused3_kernel<<<BB * HH / 2, 512, smem>>>(
        x, w_off, b_off, weight, bias, gamma, beta, rmean, rvar, out);
}

// round 5
// speedup vs baseline: 1.2201x; 1.1094x over previous
#include <cuda_runtime.h>
#include <cuda_bf16.h>
#include <math.h>

#define BB 4
#define CC 64
#define OO 64
#define HH 128
#define WW 128
#define CHS (HH * WW)

#define WPAD 68                    // main weight row floats (272B)
#define NBUF 4                     // channel ring depth

// SMEM float offsets
#define WSH_F 0
#define UNI_F (576 * WPAD)         // 39168: union {wosh 18432 | exsh 7280 | vsh 9216}
#define BN_F  (UNI_F + 18432)      // 57600
#define SMEM_FLOATS (BN_F + 128)   // 57728 floats = 230,912 B

typedef unsigned long long ull;

__device__ __forceinline__ ull pack2(float lo, float hi) {
    ull r; asm("mov.b64 %0, {%1, %2};" : "=l"(r) : "f"(lo), "f"(hi)); return r;
}
__device__ __forceinline__ void unpack2(ull v, float& lo, float& hi) {
    asm("mov.b64 {%0, %1}, %2;" : "=f"(lo), "=f"(hi) : "l"(v));
}
__device__ __forceinline__ ull ffma2(ull a, ull b, ull c) {
    ull d; asm("fma.rn.f32x2 %0, %1, %2, %3;" : "=l"(d) : "l"(a), "l"(b), "l"(c)); return d;
}

#define BAR_SYNC(id)   asm volatile("bar.sync %0, 512;"   :: "r"(id) : "memory")
#define BAR_ARRIVE(id) asm volatile("bar.arrive %0, 512;" :: "r"(id) : "memory")

// ---------------------------------------------------------------------------
// Fused DCNv2 + BN + ReLU. CTA = 2 rows (256 px), 512 threads.
// Phase 1 (offset conv): all 16 warps. Phase 2: warps 0-7 = samplers
// (gather + bilinear -> SMEM ring), warps 8-15 = consumers (FFMA2 GEMM tile).
// ---------------------------------------------------------------------------
__global__ void __launch_bounds__(512, 1) dcn_ws_kernel(
    const float* __restrict__ x,
    const float* __restrict__ w_off,
    const float* __restrict__ b_off,
    const float* __restrict__ weight,
    const float* __restrict__ bias,
    const float* __restrict__ gamma,
    const float* __restrict__ beta,
    const float* __restrict__ rmean,
    const float* __restrict__ rvar,
    float* __restrict__ out)
{
    extern __shared__ float sm[];
    float* wsh    = sm + WSH_F;    // [576][WPAD], interleaved o-layout
    float* wosh   = sm + UNI_F;    // [576][32]   (phase 1)
    float* exsh   = sm + UNI_F;    // [28][260]   (offset exchange)
    float* vsh    = sm + UNI_F;    // [NBUF][9][256] (phase 2 ring)
    float* bscale = sm + BN_F;
    float* bshift = bscale + 64;

    const int tid  = threadIdx.x;
    const int lane = tid & 31;
    const int w2   = tid >> 5;

    // ---- stage main weights with interleaved row layout ----
    // o = og*8 + ch*4 + ri  ->  row pos = ch*32 + og*4 + ri
    for (int i = tid; i < OO * 576; i += 512) {
        int o = i / 576, ck = i % 576;
        int og = o >> 3, r = o & 7, ch = r >> 2, ri = r & 3;
        wsh[ck * WPAD + ch * 32 + og * 4 + ri] = weight[i];
    }
    for (int i = tid; i < 576 * 32; i += 512) wosh[i] = 0.0f;
    if (tid < 64) {
        int o = tid;
        float sc = gamma[o] * rsqrtf(rvar[o] + 1e-5f);
        bscale[o] = sc;
        bshift[o] = (bias[o] - rmean[o]) * sc + beta[o];
    }
    __syncthreads();
    for (int i = tid; i < 27 * 576; i += 512) {
        int oc = i / 576, ck = i % 576;
        int hf = (oc >= 14), j = oc - 14 * hf;
        wosh[ck * 32 + hf * 16 + j] = w_off[i];
    }
    __syncthreads();

    const int gr0 = blockIdx.x * 2;
    const int b   = gr0 >> 7;
    const float* xb = x + (size_t)b * CC * CHS;

    // =======================================================================
    // Phase 1: offset conv (all 512 threads; lane-pair split as in R4)
    // =======================================================================
    {
        const int p     = w2 * 16 + (lane & 15);
        const int halfp = lane >> 4;
        const int hp    = (gr0 + (p >> 7)) & 127;
        const int wp_   = p & 127;

        const int ty0[5] = {-1, -1, -1, 0, 0}, tx0[5] = {-1, 0, 1, -1, 0};
        const int ty1[5] = {0, 0, 1, 1, 1},    tx1[5] = {0, 1, -1, 0, 1};
        int p1o[5]; bool p1v[5];
#pragma unroll
        for (int j = 0; j < 5; j++) {
            int ty = halfp ? ty1[j] : ty0[j];
            int tx = halfp ? tx1[j] : tx0[j];
            int y = hp + ty, xx = wp_ + tx;
            p1v[j] = (y >= 0) & (y < HH) & (xx >= 0) & (xx < WW);
            p1o[j] = y * WW + xx;
        }
        int kord[9];
#pragma unroll
        for (int i = 0; i < 9; i++) kord[i] = halfp ? (4 + i) % 9 : i;

        ull offa[7];
        {
            int chb = halfp * 14;
#pragma unroll
            for (int j = 0; j < 7; j++) {
                int i1 = chb + 2 * j + 1;
                float lo = b_off[chb + 2 * j];
                float hi = (i1 < 27) ? b_off[i1] : 0.0f;
                offa[j] = pack2(lo, hi);
            }
        }

        const float* wbase = wosh + halfp * 16;
        for (int c = 0; c < CC; c++) {
            const float* xc = xb + c * CHS;
            float xq[5];
#pragma unroll
            for (int j = 0; j < 5; j++)
                xq[j] = p1v[j] ? __ldg(xc + p1o[j]) : 0.0f;
            float r0 = __shfl_xor_sync(0xffffffffu, halfp ? xq[1] : xq[0], 16);
            float r1 = __shfl_xor_sync(0xffffffffu, halfp ? xq[2] : xq[1], 16);
            float r2 = __shfl_xor_sync(0xffffffffu, halfp ? xq[3] : xq[2], 16);
            float r3 = __shfl_xor_sync(0xffffffffu, halfp ? xq[4] : xq[3], 16);
            ull X[9];
            X[0] = pack2(xq[0], xq[0]); X[1] = pack2(xq[1], xq[1]);
            X[2] = pack2(xq[2], xq[2]); X[3] = pack2(xq[3], xq[3]);
            X[4] = pack2(xq[4], xq[4]);
            X[5] = pack2(r0, r0); X[6] = pack2(r1, r1);
            X[7] = pack2(r2, r2); X[8] = pack2(r3, r3);

            const float* crow = wbase + c * 288;
#pragma unroll
            for (int i = 0; i < 9; i++) {
                const float* wp2 = crow + kord[i] * 32;
                ulonglong2 q0 = ((const ulonglong2*)wp2)[0];
                ulonglong2 q1 = ((const ulonglong2*)wp2)[1];
                ulonglong2 q2 = ((const ulonglong2*)wp2)[2];
                ull        q6 = ((const ull*)wp2)[6];
                offa[0] = ffma2(q0.x, X[i], offa[0]);
                offa[1] = ffma2(q0.y, X[i], offa[1]);
                offa[2] = ffma2(q1.x, X[i], offa[2]);
                offa[3] = ffma2(q1.y, X[i], offa[3]);
                offa[4] = ffma2(q2.x, X[i], offa[4]);
                offa[5] = ffma2(q2.y, X[i], offa[5]);
                offa[6] = ffma2(q6,   X[i], offa[6]);
            }
        }

        __syncthreads();   // wosh reads done; exsh may overwrite
        {
            float l[14];
#pragma unroll
            for (int j = 0; j < 7; j++) unpack2(offa[j], l[2 * j], l[2 * j + 1]);
            int chb = halfp * 14;
#pragma unroll
            for (int j = 0; j < 14; j++)
                exsh[(chb + j) * 260 + p] = l[j];
        }
        __syncthreads();   // exsh ready
    }

    // =======================================================================
    // Role split
    // =======================================================================
    if (tid < 256) {
        // ----------------------- SAMPLER (producer) -----------------------
        const int spx = tid;
        const int h   = (gr0 + (spx >> 7)) & 127;
        const int w   = spx & 127;

        float cf[9][4];
        int   ofs0[9], stp[9];
#pragma unroll
        for (int k = 0; k < 9; k++) {
            float oy = exsh[(2 * k) * 260 + spx];
            float ox = exsh[(2 * k + 1) * 260 + spx];
            float m  = 1.0f / (1.0f + __expf(-exsh[(18 + k) * 260 + spx]));
            float py = (float)(h + k / 3 - 1) + oy;
            float px = (float)(w + k % 3 - 1) + ox;
            float y0f = floorf(py), x0f = floorf(px);
            float dy = py - y0f, dx = px - x0f;
            int y0 = (int)y0f, x0 = (int)x0f;
            int y1 = y0 + 1,   x1 = x0 + 1;
            bool vy0 = (y0 >= 0) & (y0 < HH), vy1 = (y1 >= 0) & (y1 < HH);
            bool vx0 = (x0 >= 0) & (x0 < WW), vx1 = (x1 >= 0) & (x1 < WW);
            int cy0 = min(max(y0, 0), HH - 1), cy1 = min(max(y1, 0), HH - 1);
            int cx0 = min(max(x0, 0), WW - 1), cx1 = min(max(x1, 0), WW - 1);
            ofs0[k] = cy0 * WW + cx0;
            stp[k]  = (((cy1 - cy0) * WW) << 16) | (cx1 - cx0);
            cf[k][0] = (vy0 && vx0) ? (1.0f - dy) * (1.0f - dx) * m : 0.0f;
            cf[k][1] = (vy0 && vx1) ? (1.0f - dy) * dx * m          : 0.0f;
            cf[k][2] = (vy1 && vx0) ? dy * (1.0f - dx) * m          : 0.0f;
            cf[k][3] = (vy1 && vx1) ? dy * dx * m                   : 0.0f;
        }
        __syncthreads();   // (A) exsh free -> vsh

        for (int c = 0; c < CC; c++) {
            int buf = c & (NBUF - 1);
            if (c >= NBUF) BAR_SYNC(1 + NBUF + buf);    // wait empty
            const float* xc = xb + c * CHS;
            float v[9];
#pragma unroll
            for (int k = 0; k < 9; k++) {
                int o0 = ofs0[k];
                int sx = stp[k] & 0xffff;
                int sy = stp[k] >> 16;
                float g0 = __ldg(xc + o0);
                float g1 = __ldg(xc + o0 + sx);
                float g2 = __ldg(xc + o0 + sy);
                float g3 = __ldg(xc + o0 + sy + sx);
                v[k] = cf[k][0] * g0 + cf[k][1] * g1
                     + cf[k][2] * g2 + cf[k][3] * g3;
            }
            float* vb = vsh + buf * 2304 + spx;
#pragma unroll
            for (int k = 0; k < 9; k++) vb[k * 256] = v[k];
            __threadfence_block();
            BAR_ARRIVE(1 + buf);                         // signal full
        }
    } else {
        // ----------------------- CONSUMER ---------------------------------
        const int ctid = tid - 256;
        const int og   = ctid & 7;     // 8 outputs: o = og*8 .. og*8+7
        const int pxg  = ctid >> 3;    // 8 px: px = pxg*8 .. pxg*8+7
        const int og4  = og * 4;

        __syncthreads();   // (A)

        ull acc[32];
#pragma unroll
        for (int j = 0; j < 32; j++) acc[j] = 0ULL;

        for (int c = 0; c < CC; c++) {
            int buf = c & (NBUF - 1);
            BAR_SYNC(1 + buf);                           // wait full
            const float* wr = wsh + c * (9 * WPAD);
            const float* vr = vsh + buf * 2304 + pxg * 8;
#pragma unroll
            for (int k = 0; k < 9; k++) {
                const float* wrk = wr + k * WPAD;
                ulonglong2 wA = *(const ulonglong2*)(wrk + og4);
                ulonglong2 wB = *(const ulonglong2*)(wrk + 32 + og4);
                const float* vrk = vr + k * 256;
                float4 a  = *(const float4*)(vrk);
                float4 bq = *(const float4*)(vrk + 4);
                ull vv0 = pack2(a.x, a.x),  vv1 = pack2(a.y, a.y);
                ull vv2 = pack2(a.z, a.z),  vv3 = pack2(a.w, a.w);
                ull vv4 = pack2(bq.x, bq.x), vv5 = pack2(bq.y, bq.y);
                ull vv6 = pack2(bq.z, bq.z), vv7 = pack2(bq.w, bq.w);
                acc[0]  = ffma2(wA.x, vv0, acc[0]);
                acc[1]  = ffma2(wA.x, vv1, acc[1]);
                acc[2]  = ffma2(wA.x, vv2, acc[2]);
                acc[3]  = ffma2(wA.x, vv3, acc[3]);
                acc[4]  = ffma2(wA.x, vv4, acc[4]);
                acc[5]  = ffma2(wA.x, vv5, acc[5]);
                acc[6]  = ffma2(wA.x, vv6, acc[6]);
                acc[7]  = ffma2(wA.x, vv7, acc[7]);
                acc[8]  = ffma2(wA.y, vv0, acc[8]);
                acc[9]  = ffma2(wA.y, vv1, acc[9]);
                acc[10] = ffma2(wA.y, vv2, acc[10]);
                acc[11] = ffma2(wA.y, vv3, acc[11]);
                acc[12] = ffma2(wA.y, vv4, acc[12]);
                acc[13] = ffma2(wA.y, vv5, acc[13]);
                acc[14] = ffma2(wA.y, vv6, acc[14]);
                acc[15] = ffma2(wA.y, vv7, acc[15]);
                acc[16] = ffma2(wB.x, vv0, acc[16]);
                acc[17] = ffma2(wB.x, vv1, acc[17]);
                acc[18] = ffma2(wB.x, vv2, acc[18]);
                acc[19] = ffma2(wB.x, vv3, acc[19]);
                acc[20] = ffma2(wB.x, vv4, acc[20]);
                acc[21] = ffma2(wB.x, vv5, acc[21]);
                acc[22] = ffma2(wB.x, vv6, acc[22]);
                acc[23] = ffma2(wB.x, vv7, acc[23]);
                acc[24] = ffma2(wB.y, vv0, acc[24]);
                acc[25] = ffma2(wB.y, vv1, acc[25]);
                acc[26] = ffma2(wB.y, vv2, acc[26]);
                acc[27] = ffma2(wB.y, vv3, acc[27]);
                acc[28] = ffma2(wB.y, vv4, acc[28]);
                acc[29] = ffma2(wB.y, vv5, acc[29]);
                acc[30] = ffma2(wB.y, vv6, acc[30]);
                acc[31] = ffma2(wB.y, vv7, acc[31]);
            }
            BAR_ARRIVE(1 + NBUF + buf);                  // signal empty
        }

        // ---- BN + ReLU + store: 8 outputs x 8 px ----
        const int px0 = pxg * 8;
        const int eh  = (gr0 + (px0 >> 7)) & 127;
        const int ew  = px0 & 127;
        float* opb = out + (size_t)b * OO * CHS + eh * WW + ew;
#pragma unroll
        for (int oi2 = 0; oi2 < 4; oi2++) {
            int o0 = og * 8 + 2 * oi2;
            float s0 = bscale[o0],     f0 = bshift[o0];
            float s1 = bscale[o0 + 1], f1 = bshift[o0 + 1];
            float lo[8], hi[8];
#pragma unroll
            for (int pj = 0; pj < 8; pj++)
                unpack2(acc[oi2 * 8 + pj], lo[pj], hi[pj]);
            float4 q0 = { fmaxf(lo[0] * s0 + f0, 0.0f), fmaxf(lo[1] * s0 + f0, 0.0f),
                          fmaxf(lo[2] * s0 + f0, 0.0f), fmaxf(lo[3] * s0 + f0, 0.0f) };
            float4 q1 = { fmaxf(lo[4] * s0 + f0, 0.0f), fmaxf(lo[5] * s0 + f0, 0.0f),
                          fmaxf(lo[6] * s0 + f0, 0.0f), fmaxf(lo[7] * s0 + f0, 0.0f) };
            float4 r0 = { fmaxf(hi[0] * s1 + f1, 0.0f), fmaxf(hi[1] * s1 + f1, 0.0f),
                          fmaxf(hi[2] * s1 + f1, 0.0f), fmaxf(hi[3] * s1 + f1, 0.0f) };
            float4 r1 = { fmaxf(hi[4] * s1 + f1, 0.0f), fmaxf(hi[5] * s1 + f1, 0.0f),
                          fmaxf(hi[6] * s1 + f1, 0.0f), fmaxf(hi[7] * s1 + f1, 0.0f) };
            *(float4*)(opb + (size_t)o0 * CHS)           = q0;
            *(float4*)(opb + (size_t)o0 * CHS + 4)       = q1;
            *(float4*)(opb + (size_t)(o0 + 1) * CHS)     = r0;
            *(float4*)(opb + (size_t)(o0 + 1) * CHS + 4) = r1;
        }
    }
}

// ---------------------------------------------------------------------------

extern "C" void kernel_launch(void* const* d_in, const int* in_sizes, int n_in,
                              void* d_out, int out_size)
{
    const float* x      = (const float*)d_in[0];
    const float* w_off  = (const float*)d_in[1];
    const float* b_off  = (const float*)d_in[2];
    const float* weight = (const float*)d_in[3];
    const float* bias   = (const float*)d_in[4];
    const float* gamma  = (const float*)d_in[5];
    const float* beta   = (const float*)d_in[6];
    const float* rmean  = (const float*)d_in[7];
    const float* rvar   = (const float*)d_in[8];
    float* out = (float*)d_out;

    const int smem = SMEM_FLOATS * sizeof(float);   // 230,912 B

    cudaFuncSetAttribute(dcn_ws_kernel,
                         cudaFuncAttributeMaxDynamicSharedMemorySize, smem);

    dcn_ws_kernel<<<BB * HH / 2, 512, smem>>>(
        x, w_off, b_off, weight, bias, gamma, beta, rmean, rvar, out);
}

// round 6
// speedup vs baseline: 1.2224x; 1.0019x over previous
#include <cuda_runtime.h>
#include <cuda_bf16.h>
#include <math.h>

#define BB 4
#define CC 64
#define OO 64
#define HH 128
#define WW 128
#define CHS (HH * WW)

#define WPAD 68                    // main weight row floats (272B)
#define NBUF 4                     // channel ring depth

// SMEM float offsets
#define WSH_F 0
#define UNI_F (576 * WPAD)         // 39168: union {wosh 18432 | exsh 7280 | vsh 9216}
#define BN_F  (UNI_F + 18432)      // 57600
#define SMEM_FLOATS (BN_F + 128)   // 57728 floats = 230,912 B

typedef unsigned long long ull;

__device__ __forceinline__ ull pack2(float lo, float hi) {
    ull r; asm("mov.b64 %0, {%1, %2};" : "=l"(r) : "f"(lo), "f"(hi)); return r;
}
__device__ __forceinline__ void unpack2(ull v, float& lo, float& hi) {
    asm("mov.b64 {%0, %1}, %2;" : "=f"(lo), "=f"(hi) : "l"(v));
}
__device__ __forceinline__ ull ffma2(ull a, ull b, ull c) {
    ull d; asm("fma.rn.f32x2 %0, %1, %2, %3;" : "=l"(d) : "l"(a), "l"(b), "l"(c)); return d;
}

#define BAR_SYNC(id)   asm volatile("bar.sync %0, 512;"   :: "r"(id) : "memory")
#define BAR_ARRIVE(id) asm volatile("bar.arrive %0, 512;" :: "r"(id) : "memory")

// ---------------------------------------------------------------------------
// Fused DCNv2 + BN + ReLU. CTA = 2 rows (256 px), 512 threads.
// Phase 1 (offset conv): all 16 warps. Phase 2: warps 0-7 = samplers
// (gather + bilinear -> SMEM ring), warps 8-15 = consumers (FFMA2 GEMM tile).
// ---------------------------------------------------------------------------
__global__ void __launch_bounds__(512, 1) dcn_ws_kernel(
    const float* __restrict__ x,
    const float* __restrict__ w_off,
    const float* __restrict__ b_off,
    const float* __restrict__ weight,
    const float* __restrict__ bias,
    const float* __restrict__ gamma,
    const float* __restrict__ beta,
    const float* __restrict__ rmean,
    const float* __restrict__ rvar,
    float* __restrict__ out)
{
    extern __shared__ float sm[];
    float* wsh    = sm + WSH_F;    // [576][WPAD], interleaved o-layout
    float* wosh   = sm + UNI_F;    // [576][32]   (phase 1)
    float* exsh   = sm + UNI_F;    // [28][260]   (offset exchange)
    float* vsh    = sm + UNI_F;    // [NBUF][9][256] (phase 2 ring)
    float* bscale = sm + BN_F;
    float* bshift = bscale + 64;

    const int tid  = threadIdx.x;
    const int lane = tid & 31;
    const int w2   = tid >> 5;

    // ---- stage main weights with interleaved row layout ----
    // o = og*8 + ch*4 + ri  ->  row pos = ch*32 + og*4 + ri
    for (int i = tid; i < OO * 576; i += 512) {
        int o = i / 576, ck = i % 576;
        int og = o >> 3, r = o & 7, ch = r >> 2, ri = r & 3;
        wsh[ck * WPAD + ch * 32 + og * 4 + ri] = weight[i];
    }
    for (int i = tid; i < 576 * 32; i += 512) wosh[i] = 0.0f;
    if (tid < 64) {
        int o = tid;
        float sc = gamma[o] * rsqrtf(rvar[o] + 1e-5f);
        bscale[o] = sc;
        bshift[o] = (bias[o] - rmean[o]) * sc + beta[o];
    }
    __syncthreads();
    for (int i = tid; i < 27 * 576; i += 512) {
        int oc = i / 576, ck = i % 576;
        int hf = (oc >= 14), j = oc - 14 * hf;
        wosh[ck * 32 + hf * 16 + j] = w_off[i];
    }
    __syncthreads();

    const int gr0 = blockIdx.x * 2;
    const int b   = gr0 >> 7;
    const float* xb = x + (size_t)b * CC * CHS;

    // =======================================================================
    // Phase 1: offset conv (all 512 threads; lane-pair split as in R4)
    // =======================================================================
    {
        const int p     = w2 * 16 + (lane & 15);
        const int halfp = lane >> 4;
        const int hp    = (gr0 + (p >> 7)) & 127;
        const int wp_   = p & 127;

        const int ty0[5] = {-1, -1, -1, 0, 0}, tx0[5] = {-1, 0, 1, -1, 0};
        const int ty1[5] = {0, 0, 1, 1, 1},    tx1[5] = {0, 1, -1, 0, 1};
        int p1o[5]; bool p1v[5];
#pragma unroll
        for (int j = 0; j < 5; j++) {
            int ty = halfp ? ty1[j] : ty0[j];
            int tx = halfp ? tx1[j] : tx0[j];
            int y = hp + ty, xx = wp_ + tx;
            p1v[j] = (y >= 0) & (y < HH) & (xx >= 0) & (xx < WW);
            p1o[j] = y * WW + xx;
        }
        int kord[9];
#pragma unroll
        for (int i = 0; i < 9; i++) kord[i] = halfp ? (4 + i) % 9 : i;

        ull offa[7];
        {
            int chb = halfp * 14;
#pragma unroll
            for (int j = 0; j < 7; j++) {
                int i1 = chb + 2 * j + 1;
                float lo = b_off[chb + 2 * j];
                float hi = (i1 < 27) ? b_off[i1] : 0.0f;
                offa[j] = pack2(lo, hi);
            }
        }

        const float* wbase = wosh + halfp * 16;
        for (int c = 0; c < CC; c++) {
            const float* xc = xb + c * CHS;
            float xq[5];
#pragma unroll
            for (int j = 0; j < 5; j++)
                xq[j] = p1v[j] ? __ldg(xc + p1o[j]) : 0.0f;
            float r0 = __shfl_xor_sync(0xffffffffu, halfp ? xq[1] : xq[0], 16);
            float r1 = __shfl_xor_sync(0xffffffffu, halfp ? xq[2] : xq[1], 16);
            float r2 = __shfl_xor_sync(0xffffffffu, halfp ? xq[3] : xq[2], 16);
            float r3 = __shfl_xor_sync(0xffffffffu, halfp ? xq[4] : xq[3], 16);
            ull X[9];
            X[0] = pack2(xq[0], xq[0]); X[1] = pack2(xq[1], xq[1]);
            X[2] = pack2(xq[2], xq[2]); X[3] = pack2(xq[3], xq[3]);
            X[4] = pack2(xq[4], xq[4]);
            X[5] = pack2(r0, r0); X[6] = pack2(r1, r1);
            X[7] = pack2(r2, r2); X[8] = pack2(r3, r3);

            const float* crow = wbase + c * 288;
#pragma unroll
            for (int i = 0; i < 9; i++) {
                const float* wp2 = crow + kord[i] * 32;
                ulonglong2 q0 = ((const ulonglong2*)wp2)[0];
                ulonglong2 q1 = ((const ulonglong2*)wp2)[1];
                ulonglong2 q2 = ((const ulonglong2*)wp2)[2];
                ull        q6 = ((const ull*)wp2)[6];
                offa[0] = ffma2(q0.x, X[i], offa[0]);
                offa[1] = ffma2(q0.y, X[i], offa[1]);
                offa[2] = ffma2(q1.x, X[i], offa[2]);
                offa[3] = ffma2(q1.y, X[i], offa[3]);
                offa[4] = ffma2(q2.x, X[i], offa[4]);
                offa[5] = ffma2(q2.y, X[i], offa[5]);
                offa[6] = ffma2(q6,   X[i], offa[6]);
            }
        }

        __syncthreads();   // wosh reads done; exsh may overwrite
        {
            float l[14];
#pragma unroll
            for (int j = 0; j < 7; j++) unpack2(offa[j], l[2 * j], l[2 * j + 1]);
            int chb = halfp * 14;
#pragma unroll
            for (int j = 0; j < 14; j++)
                exsh[(chb + j) * 260 + p] = l[j];
        }
        __syncthreads();   // exsh ready
    }

    // =======================================================================
    // Role split
    // =======================================================================
    if (tid < 256) {
        // ----------------------- SAMPLER (producer) -----------------------
        const int spx = tid;
        const int h   = (gr0 + (spx >> 7)) & 127;
        const int w   = spx & 127;

        float cf[9][4];
        int   ofs0[9], stp[9];
#pragma unroll
        for (int k = 0; k < 9; k++) {
            float oy = exsh[(2 * k) * 260 + spx];
            float ox = exsh[(2 * k + 1) * 260 + spx];
            float m  = 1.0f / (1.0f + __expf(-exsh[(18 + k) * 260 + spx]));
            float py = (float)(h + k / 3 - 1) + oy;
            float px = (float)(w + k % 3 - 1) + ox;
            float y0f = floorf(py), x0f = floorf(px);
            float dy = py - y0f, dx = px - x0f;
            int y0 = (int)y0f, x0 = (int)x0f;
            int y1 = y0 + 1,   x1 = x0 + 1;
            bool vy0 = (y0 >= 0) & (y0 < HH), vy1 = (y1 >= 0) & (y1 < HH);
            bool vx0 = (x0 >= 0) & (x0 < WW), vx1 = (x1 >= 0) & (x1 < WW);
            int cy0 = min(max(y0, 0), HH - 1), cy1 = min(max(y1, 0), HH - 1);
            int cx0 = min(max(x0, 0), WW - 1), cx1 = min(max(x1, 0), WW - 1);
            ofs0[k] = cy0 * WW + cx0;
            stp[k]  = (((cy1 - cy0) * WW) << 16) | (cx1 - cx0);
            cf[k][0] = (vy0 && vx0) ? (1.0f - dy) * (1.0f - dx) * m : 0.0f;
            cf[k][1] = (vy0 && vx1) ? (1.0f - dy) * dx * m          : 0.0f;
            cf[k][2] = (vy1 && vx0) ? dy * (1.0f - dx) * m          : 0.0f;
            cf[k][3] = (vy1 && vx1) ? dy * dx * m                   : 0.0f;
        }
        __syncthreads();   // (A) exsh free -> vsh

        for (int c = 0; c < CC; c++) {
            int buf = c & (NBUF - 1);
            if (c >= NBUF) BAR_SYNC(1 + NBUF + buf);    // wait empty
            const float* xc = xb + c * CHS;
            float v[9];
#pragma unroll
            for (int k = 0; k < 9; k++) {
                int o0 = ofs0[k];
                int sx = stp[k] & 0xffff;
                int sy = stp[k] >> 16;
                float g0 = __ldg(xc + o0);
                float g1 = __ldg(xc + o0 + sx);
                float g2 = __ldg(xc + o0 + sy);
                float g3 = __ldg(xc + o0 + sy + sx);
                v[k] = cf[k][0] * g0 + cf[k][1] * g1
                     + cf[k][2] * g2 + cf[k][3] * g3;
            }
            float* vb = vsh + buf * 2304 + spx;
#pragma unroll
            for (int k = 0; k < 9; k++) vb[k * 256] = v[k];
            __threadfence_block();
            BAR_ARRIVE(1 + buf);                         // signal full
        }
    } else {
        // ----------------------- CONSUMER ---------------------------------
        const int ctid = tid - 256;
        const int og   = ctid & 7;     // 8 outputs: o = og*8 .. og*8+7
        const int pxg  = ctid >> 3;    // 8 px: px = pxg*8 .. pxg*8+7
        const int og4  = og * 4;

        __syncthreads();   // (A)

        ull acc[32];
#pragma unroll
        for (int j = 0; j < 32; j++) acc[j] = 0ULL;

        for (int c = 0; c < CC; c++) {
            int buf = c & (NBUF - 1);
            BAR_SYNC(1 + buf);                           // wait full
            const float* wr = wsh + c * (9 * WPAD);
            const float* vr = vsh + buf * 2304 + pxg * 8;
#pragma unroll
            for (int k = 0; k < 9; k++) {
                const float* wrk = wr + k * WPAD;
                ulonglong2 wA = *(const ulonglong2*)(wrk + og4);
                ulonglong2 wB = *(const ulonglong2*)(wrk + 32 + og4);
                const float* vrk = vr + k * 256;
                float4 a  = *(const float4*)(vrk);
                float4 bq = *(const float4*)(vrk + 4);
                ull vv0 = pack2(a.x, a.x),  vv1 = pack2(a.y, a.y);
                ull vv2 = pack2(a.z, a.z),  vv3 = pack2(a.w, a.w);
                ull vv4 = pack2(bq.x, bq.x), vv5 = pack2(bq.y, bq.y);
                ull vv6 = pack2(bq.z, bq.z), vv7 = pack2(bq.w, bq.w);
                acc[0]  = ffma2(wA.x, vv0, acc[0]);
                acc[1]  = ffma2(wA.x, vv1, acc[1]);
                acc[2]  = ffma2(wA.x, vv2, acc[2]);
                acc[3]  = ffma2(wA.x, vv3, acc[3]);
                acc[4]  = ffma2(wA.x, vv4, acc[4]);
                acc[5]  = ffma2(wA.x, vv5, acc[5]);
                acc[6]  = ffma2(wA.x, vv6, acc[6]);
                acc[7]  = ffma2(wA.x, vv7, acc[7]);
                acc[8]  = ffma2(wA.y, vv0, acc[8]);
                acc[9]  = ffma2(wA.y, vv1, acc[9]);
                acc[10] = ffma2(wA.y, vv2, acc[10]);
                acc[11] = ffma2(wA.y, vv3, acc[11]);
                acc[12] = ffma2(wA.y, vv4, acc[12]);
                acc[13] = ffma2(wA.y, vv5, acc[13]);
                acc[14] = ffma2(wA.y, vv6, acc[14]);
                acc[15] = ffma2(wA.y, vv7, acc[15]);
                acc[16] = ffma2(wB.x, vv0, acc[16]);
                acc[17] = ffma2(wB.x, vv1, acc[17]);
                acc[18] = ffma2(wB.x, vv2, acc[18]);
                acc[19] = ffma2(wB.x, vv3, acc[19]);
                acc[20] = ffma2(wB.x, vv4, acc[20]);
                acc[21] = ffma2(wB.x, vv5, acc[21]);
                acc[22] = ffma2(wB.x, vv6, acc[22]);
                acc[23] = ffma2(wB.x, vv7, acc[23]);
                acc[24] = ffma2(wB.y, vv0, acc[24]);
                acc[25] = ffma2(wB.y, vv1, acc[25]);
                acc[26] = ffma2(wB.y, vv2, acc[26]);
                acc[27] = ffma2(wB.y, vv3, acc[27]);
                acc[28] = ffma2(wB.y, vv4, acc[28]);
                acc[29] = ffma2(wB.y, vv5, acc[29]);
                acc[30] = ffma2(wB.y, vv6, acc[30]);
                acc[31] = ffma2(wB.y, vv7, acc[31]);
            }
            BAR_ARRIVE(1 + NBUF + buf);                  // signal empty
        }

        // ---- BN + ReLU + store: 8 outputs x 8 px ----
        const int px0 = pxg * 8;
        const int eh  = (gr0 + (px0 >> 7)) & 127;
        const int ew  = px0 & 127;
        float* opb = out + (size_t)b * OO * CHS + eh * WW + ew;
#pragma unroll
        for (int oi2 = 0; oi2 < 4; oi2++) {
            int o0 = og * 8 + 2 * oi2;
            float s0 = bscale[o0],     f0 = bshift[o0];
            float s1 = bscale[o0 + 1], f1 = bshift[o0 + 1];
            float lo[8], hi[8];
#pragma unroll
            for (int pj = 0; pj < 8; pj++)
                unpack2(acc[oi2 * 8 + pj], lo[pj], hi[pj]);
            float4 q0 = { fmaxf(lo[0] * s0 + f0, 0.0f), fmaxf(lo[1] * s0 + f0, 0.0f),
                          fmaxf(lo[2] * s0 + f0, 0.0f), fmaxf(lo[3] * s0 + f0, 0.0f) };
            float4 q1 = { fmaxf(lo[4] * s0 + f0, 0.0f), fmaxf(lo[5] * s0 + f0, 0.0f),
                          fmaxf(lo[6] * s0 + f0, 0.0f), fmaxf(lo[7] * s0 + f0, 0.0f) };
            float4 r0 = { fmaxf(hi[0] * s1 + f1, 0.0f), fmaxf(hi[1] * s1 + f1, 0.0f),
                          fmaxf(hi[2] * s1 + f1, 0.0f), fmaxf(hi[3] * s1 + f1, 0.0f) };
            float4 r1 = { fmaxf(hi[4] * s1 + f1, 0.0f), fmaxf(hi[5] * s1 + f1, 0.0f),
                          fmaxf(hi[6] * s1 + f1, 0.0f), fmaxf(hi[7] * s1 + f1, 0.0f) };
            *(float4*)(opb + (size_t)o0 * CHS)           = q0;
            *(float4*)(opb + (size_t)o0 * CHS + 4)       = q1;
            *(float4*)(opb + (size_t)(o0 + 1) * CHS)     = r0;
            *(float4*)(opb + (size_t)(o0 + 1) * CHS + 4) = r1;
        }
    }
}

// ---------------------------------------------------------------------------

extern "C" void kernel_launch(void* const* d_in, const int* in_sizes, int n_in,
                              void* d_out, int out_size)
{
    const float* x      = (const float*)d_in[0];
    const float* w_off  = (const float*)d_in[1];
    const float* b_off  = (const float*)d_in[2];
    const float* weight = (const float*)d_in[3];
    const float* bias   = (const float*)d_in[4];
    const float* gamma  = (const float*)d_in[5];
    const float* beta   = (const float*)d_in[6];
    const float* rmean  = (const float*)d_in[7];
    const float* rvar   = (const float*)d_in[8];
    float* out = (float*)d_out;

    const int smem = SMEM_FLOATS * sizeof(float);   // 230,912 B

    cudaFuncSetAttribute(dcn_ws_kernel,
                         cudaFuncAttributeMaxDynamicSharedMemorySize, smem);

    dcn_ws_kernel<<<BB * HH / 2, 512, smem>>>(
        x, w_off, b_off, weight, bias, gamma, beta, rmean, rvar, out);
}